// round 2
// baseline (speedup 1.0000x reference)
#include <cuda_runtime.h>
#include <math.h>

#define BB 128
#define CC 49
#define NN 3136
#define HH 56

// ---------------- scratch (device globals; no allocations allowed) ----------
__device__ float g_v[BB*NN];              // v[b][n] = mean over channels
__device__ float g_q[BB*CC*CC];           // q[b][o][p]
__device__ float g_qW[BB*CC*CC];          // qW[b][c][j]
__device__ float g_qb[BB*CC];             // qb[b][c]
__device__ float g_amax_part[BB*7*CC];    // per-chunk maxima
__device__ float g_amax[BB*CC];           // final max + qb
__device__ float g_spart[8*NN*BB];        // k-split partials of s[m][b]

// ---------------- kernel 1: v[b,n] = mean_c x[b,c,n] ------------------------
__global__ void k_v(const float* __restrict__ x) {
    int idx = blockIdx.x * blockDim.x + threadIdx.x;   // over B*N (exact)
    int b = idx / NN, n = idx - b * NN;
    const float* xb = x + (size_t)b * CC * NN + n;
    float s = 0.f;
#pragma unroll
    for (int c = 0; c < CC; c++) s += xb[c * NN];
    g_v[idx] = s * (1.0f / 49.0f);
}

// ---------------- kernel 2: q conv (Conv2d 8x8 stride 8) --------------------
// One block per batch, 256 threads. 4 channels staged per stage (13 stages).
// Active threads: (49 output tiles) x (4 channel slots) = 196.
#define IMG_R 57                   // padded row stride (bank spread)
#define IMG_S (HH*IMG_R)           // 3192 floats per channel
#define WQ_OS 65                   // padded per-o stride for wq
#define WQ_CS (CC*WQ_OS)           // 3185 floats per channel
#define QCONV_SMEM ((4*IMG_S + 4*WQ_CS)*4)   // ~102 KB

__global__ __launch_bounds__(256, 1) void k_qconv(const float* __restrict__ x,
                                                  const float* __restrict__ Wq) {
    extern __shared__ float sm[];
    float* simg = sm;               // 4 * IMG_S
    float* swq  = sm + 4 * IMG_S;   // 4 * WQ_CS
    int b = blockIdx.x;
    int t = threadIdx.x;
    int tt = t % 49;                // output tile index (7x7 grid of tiles)
    int cs = t / 49;                // channel slot 0..3 (t<196)
    int to = tt / 7;                // o-group: o = 7*to + a
    int tp = tt % 7;                // ph (pw = j)
    bool active = (t < 196);

    float acc[49];
#pragma unroll
    for (int i = 0; i < 49; i++) acc[i] = 0.f;

    const float* xb = x + (size_t)b * CC * NN;

    for (int st = 0; st < 13; st++) {
        __syncthreads();
        int cbase = st * 4;
        // stage 4 channel images (row-padded)
        for (int e = t; e < 4 * NN; e += 256) {
            int chn = e / NN, n = e - chn * NN;
            int h = n / HH, w = n - h * HH;
            int gi = cbase + chn;
            simg[chn * IMG_S + h * IMG_R + w] = (gi < CC) ? xb[gi * NN + n] : 0.f;
        }
        // stage 4 channels of Wq: Wq[o][i][k], k = kh*8+kw
        for (int e = t; e < 4 * CC * 64; e += 256) {
            int chn = e / (CC * 64);
            int r = e - chn * (CC * 64);
            int o = r >> 6, k = r & 63;
            int gi = cbase + chn;
            swq[chn * WQ_CS + o * WQ_OS + k] = (gi < CC) ? Wq[o * (CC * 64) + gi * 64 + k] : 0.f;
        }
        __syncthreads();
        if (active) {
            const float* img = simg + cs * IMG_S + (8 * tp) * IMG_R;
            const float* wqc = swq + cs * WQ_CS + (to * 7) * WQ_OS;
#pragma unroll 2
            for (int k = 0; k < 64; k++) {
                int kh = k >> 3, kw = k & 7;
                float iv[7], wv[7];
#pragma unroll
                for (int j = 0; j < 7; j++) iv[j] = img[kh * IMG_R + 8 * j + kw];
#pragma unroll
                for (int a = 0; a < 7; a++) wv[a] = wqc[a * WQ_OS + k];
#pragma unroll
                for (int a = 0; a < 7; a++)
#pragma unroll
                    for (int j = 0; j < 7; j++)
                        acc[a * 7 + j] += wv[a] * iv[j];
            }
        }
    }
    // cross-slot reduction (4 channel slots per tile)
    __syncthreads();
    float* sred = sm;               // 49*49*4 = 9604 floats
    if (active) {
#pragma unroll
        for (int i = 0; i < 49; i++) sred[(tt * 49 + i) * 4 + cs] = acc[i];
    }
    __syncthreads();
    for (int e = t; e < 2401; e += 256) {
        float s = 0.f;
#pragma unroll
        for (int c4 = 0; c4 < 4; c4++) s += sred[e * 4 + c4];
        int tile = e / 49, w = e - tile * 49;
        int o = (tile / 7) * 7 + (w / 7);
        int p = (tile % 7) * 7 + (w % 7);
        g_q[(b * CC + o) * CC + p] = s;
    }
}

// ---------------- kernel 3: qW[b,c,j] = sum_p q[b,c,p]*Wsr[p,j]; qb ---------
__global__ void k_qw(const float* __restrict__ Wsr, const float* __restrict__ bsr) {
    __shared__ float sq[CC * CC], sw[CC * CC], sb[CC];
    int b = blockIdx.x, t = threadIdx.x;  // 256 threads
    for (int e = t; e < CC * CC; e += 256) { sq[e] = g_q[b * CC * CC + e]; sw[e] = Wsr[e]; }
    if (t < CC) sb[t] = bsr[t];
    __syncthreads();
    for (int e = t; e < CC * CC; e += 256) {
        int c = e / CC, j = e - c * CC;
        float s = 0.f;
#pragma unroll
        for (int p = 0; p < CC; p++) s += sq[c * CC + p] * sw[p * CC + j];
        g_qW[b * CC * CC + e] = s;
    }
    if (t < CC) {
        float s = 0.f;
#pragma unroll
        for (int p = 0; p < CC; p++) s += sq[t * CC + p] * sb[p];
        g_qb[b * CC + t] = s;
    }
}

// ---------------- kernel 4: amax_part = max_n sum_j qW[c,j]*x[b,j,n] --------
// grid (B, 7 col-chunks of 512, 2 c-halves of 25/24). Each thread: 2 columns,
// 25 channels -> 50 accumulators, no spills. LDS:FMA = 1:2.
__global__ __launch_bounds__(256) void k_amax(const float* __restrict__ x) {
    __shared__ float sqw[50 * 50];            // padded; row 49 zeroed
    int b = blockIdx.x, chk = blockIdx.y, half = blockIdx.z;
    int c0 = half * 25;
    int nc = half ? 24 : 25;
    int t = threadIdx.x;
    for (int e = t; e < 50 * 50; e += 256) {
        int c = e / 50, j = e - c * 50;
        sqw[e] = (c < CC && j < CC) ? g_qW[(b * CC + c) * CC + j] : 0.f;
    }
    __syncthreads();
    int n0 = chk * 512 + t;
    int n1 = n0 + 256;
    bool v0 = n0 < NN, v1 = n1 < NN;
    const float* xb = x + (size_t)b * CC * NN;
    float a0[25], a1[25];
#pragma unroll
    for (int c = 0; c < 25; c++) { a0[c] = 0.f; a1[c] = 0.f; }
    for (int j = 0; j < CC; j++) {
        float x0 = v0 ? xb[j * NN + n0] : 0.f;
        float x1 = v1 ? xb[j * NN + n1] : 0.f;
        const float* wrow = sqw + c0 * 50 + j;
#pragma unroll
        for (int c = 0; c < 25; c++) {
            float wv = wrow[c * 50];          // warp-broadcast LDS
            a0[c] += wv * x0;
            a1[c] += wv * x1;
        }
    }
#pragma unroll
    for (int c = 0; c < 25; c++) {
        float mm = -INFINITY;
        if (v0) mm = a0[c];
        if (v1) mm = fmaxf(mm, a1[c]);
        a0[c] = mm;
    }
    // warp-level max reduce
#pragma unroll
    for (int c = 0; c < 25; c++) {
#pragma unroll
        for (int off = 16; off > 0; off >>= 1)
            a0[c] = fmaxf(a0[c], __shfl_xor_sync(0xffffffffu, a0[c], off));
    }
    __shared__ float wr[8][25];
    int lane = t & 31, wid = t >> 5;
    if (lane == 0) {
#pragma unroll
        for (int c = 0; c < 25; c++) wr[wid][c] = a0[c];
    }
    __syncthreads();
    if (t < nc) {
        float mm = wr[0][t];
#pragma unroll
        for (int w2 = 1; w2 < 8; w2++) mm = fmaxf(mm, wr[w2][t]);
        g_amax_part[(b * 7 + chk) * CC + c0 + t] = mm;
    }
}

// ---------------- kernel 4b: final max over chunks + qb ----------------------
__global__ void k_amax2() {
    int idx = blockIdx.x * blockDim.x + threadIdx.x;
    if (idx >= BB * CC) return;
    int b = idx / CC;
    float m = -INFINITY;
#pragma unroll
    for (int ch = 0; ch < 7; ch++) m = fmaxf(m, g_amax_part[(b * 7 + ch) * CC + (idx - b * CC)]);
    g_amax[idx] = m + g_qb[idx];
}

// ---------------- kernel 5: s[m,b] = sum_k Wproj[m,k]*v[b,k]  (k-split x8) ---
#define MT 112
#define NT 64
#define KT 28
__global__ __launch_bounds__(256, 4) void k_gemm(const float* __restrict__ Wproj) {
    __shared__ float sA[KT * 113];   // [k][m] padded
    __shared__ float sB[KT * 65];    // [k][n] padded
    int m0 = blockIdx.x * MT, n0 = blockIdx.y * NT, k0 = blockIdx.z * 392;
    int t = threadIdx.x;
    int tx = t & 15, ty = t >> 4;
    float acc[7][4];
#pragma unroll
    for (int u = 0; u < 7; u++)
#pragma unroll
        for (int w = 0; w < 4; w++) acc[u][w] = 0.f;

    for (int ks = 0; ks < 14; ks++) {
        int kb = k0 + ks * KT;
        __syncthreads();
        for (int e = t; e < MT * KT; e += 256) {
            int ml = e / KT, kk = e - ml * KT;
            sA[kk * 113 + ml] = Wproj[(size_t)(m0 + ml) * NN + kb + kk];
        }
        for (int e = t; e < NT * KT; e += 256) {
            int nl = e / KT, kk = e - nl * KT;
            sB[kk * 65 + nl] = g_v[(n0 + nl) * NN + kb + kk];
        }
        __syncthreads();
#pragma unroll 4
        for (int kk = 0; kk < KT; kk++) {
            float av[7], bv[4];
#pragma unroll
            for (int u = 0; u < 7; u++) av[u] = sA[kk * 113 + tx + 16 * u];
#pragma unroll
            for (int w = 0; w < 4; w++) bv[w] = sB[kk * 65 + ty + 16 * w];
#pragma unroll
            for (int u = 0; u < 7; u++)
#pragma unroll
                for (int w = 0; w < 4; w++) acc[u][w] += av[u] * bv[w];
        }
    }
    float* sp = g_spart + (size_t)blockIdx.z * NN * BB;
#pragma unroll
    for (int u = 0; u < 7; u++)
#pragma unroll
        for (int w = 0; w < 4; w++)
            sp[(m0 + tx + 16 * u) * BB + (n0 + ty + 16 * w)] = acc[u][w];
}

// ---------------- kernel 6: out[b,m,c] = amax[b,c] * sum_ks spart[ks][m,b] ---
__global__ void k_out(float* __restrict__ out) {
    __shared__ float sa[CC];
    __shared__ float ss[64];
    int b = blockIdx.x, mt = blockIdx.y, t = threadIdx.x;  // 256 threads
    if (t < CC) sa[t] = g_amax[b * CC + t];
    if (t < 64) {
        int m = mt * 64 + t;
        float s = 0.f;
#pragma unroll
        for (int ks = 0; ks < 8; ks++) s += g_spart[(size_t)ks * NN * BB + m * BB + b];
        ss[t] = s;
    }
    __syncthreads();
    float* ob = out + ((size_t)b * NN + mt * 64) * CC;
    for (int e = t; e < 64 * CC; e += 256) {
        int m = e / CC, c = e - m * CC;
        ob[e] = ss[m] * sa[c];
    }
}

// ---------------- launch -----------------------------------------------------
extern "C" void kernel_launch(void* const* d_in, const int* in_sizes, int n_in,
                              void* d_out, int out_size) {
    const float *x = nullptr, *Wq = nullptr, *Wsr = nullptr, *bsr = nullptr, *Wproj = nullptr;
    for (int i = 0; i < n_in; i++) {
        switch (in_sizes[i]) {
            case BB * CC * NN: x     = (const float*)d_in[i]; break;  // 19668992
            case CC * CC * 64: Wq    = (const float*)d_in[i]; break;  // 153664
            case CC * CC:      Wsr   = (const float*)d_in[i]; break;  // 2401
            case CC:           bsr   = (const float*)d_in[i]; break;  // 49
            case NN * NN:      Wproj = (const float*)d_in[i]; break;  // 9834496
            default: break;                                           // H, W scalars ignored
        }
    }
    cudaFuncSetAttribute(k_qconv, cudaFuncAttributeMaxDynamicSharedMemorySize, QCONV_SMEM);

    k_v    <<<(BB * NN) / 256, 256>>>(x);
    k_qconv<<<BB, 256, QCONV_SMEM>>>(x, Wq);
    k_qw   <<<BB, 256>>>(Wsr, bsr);
    k_amax <<<dim3(BB, 7, 2), 256>>>(x);
    k_amax2<<<(BB * CC + 255) / 256, 256>>>();
    k_gemm <<<dim3(NN / MT, BB / NT, 8), 256>>>(Wproj);
    k_out  <<<dim3(BB, NN / 64), 256>>>((float*)d_out);
}